// round 3
// baseline (speedup 1.0000x reference)
#include <cuda_runtime.h>
#include <math.h>

#define NN   2048
#define CC   64
#define NT   256          // threads per block (= j columns per block)
#define ICH  8            // i rows per block
#define GX   (NN / NT)    // 8
#define GY   (NN / ICH)   // 256
#define NBLK (GX * GY)    // 2048
#define NBUCK 64

__device__ double   g_accs[NBUCK];  // zero at load; reset by last block
__device__ unsigned g_count;        // zero at load; reset by last block

__device__ __forceinline__ float sqrt_approx(float x) {
    float r; asm("sqrt.approx.f32 %0, %1;" : "=f"(r) : "f"(x)); return r;
}
__device__ __forceinline__ float rcp_approx(float x) {
    float r; asm("rcp.approx.f32 %0, %1;" : "=f"(r) : "f"(x)); return r;
}

__global__ void __launch_bounds__(NT) fused_kernel(
    const float* __restrict__ X,     // (N,3)
    const float* __restrict__ embs,  // (N,C)
    const float* __restrict__ w0,    // (N,)
    const float* __restrict__ s0,    // (N,)
    const float* __restrict__ mask,  // (N,N)
    const float* __restrict__ df,    // (2C,)
    const float* __restrict__ rf,    // (2C,)
    float* __restrict__ out)
{
    const int tid  = threadIdx.x;
    const int lane = tid & 31;
    const int wid  = tid >> 5;          // 0..7
    const int j    = blockIdx.x * NT + tid;
    const int i0   = blockIdx.y * ICH;

    __shared__ float4 sPosI[ICH];   // x,y,z,s0
    __shared__ float4 sMiscI[ICH];  // w0, exp(-r_hi), exp(-d_hi), pad
    __shared__ float  sred[NT];

    // ---- phase A1: prefetch this thread's 8 mask values (MLP=8) ----
    float mk[ICH];
#pragma unroll
    for (int k = 0; k < ICH; k++)
        mk[k] = __ldg(mask + (size_t)(i0 + k) * NN + j);

    // ---- phase A2: j-side per-node precompute (dot vs LOW halves) ----
    float rlo0 = 0.f, rlo1 = 0.f, dlo0 = 0.f, dlo1 = 0.f;
    {
        const float4* ej = (const float4*)(embs + (size_t)j * CC);
#pragma unroll
        for (int c = 0; c < CC / 8; c++) {
            const float4 a = ej[2*c], b = ej[2*c+1];
            rlo0 = fmaf(a.x, __ldg(rf + 8*c + 0), rlo0);
            rlo0 = fmaf(a.y, __ldg(rf + 8*c + 1), rlo0);
            rlo0 = fmaf(a.z, __ldg(rf + 8*c + 2), rlo0);
            rlo0 = fmaf(a.w, __ldg(rf + 8*c + 3), rlo0);
            rlo1 = fmaf(b.x, __ldg(rf + 8*c + 4), rlo1);
            rlo1 = fmaf(b.y, __ldg(rf + 8*c + 5), rlo1);
            rlo1 = fmaf(b.z, __ldg(rf + 8*c + 6), rlo1);
            rlo1 = fmaf(b.w, __ldg(rf + 8*c + 7), rlo1);
            dlo0 = fmaf(a.x, __ldg(df + 8*c + 0), dlo0);
            dlo0 = fmaf(a.y, __ldg(df + 8*c + 1), dlo0);
            dlo0 = fmaf(a.z, __ldg(df + 8*c + 2), dlo0);
            dlo0 = fmaf(a.w, __ldg(df + 8*c + 3), dlo0);
            dlo1 = fmaf(b.x, __ldg(df + 8*c + 4), dlo1);
            dlo1 = fmaf(b.y, __ldg(df + 8*c + 5), dlo1);
            dlo1 = fmaf(b.z, __ldg(df + 8*c + 6), dlo1);
            dlo1 = fmaf(b.w, __ldg(df + 8*c + 7), dlo1);
        }
    }
    const float xj  = X[3*j], yj = X[3*j+1], zj = X[3*j+2];
    const float s0j = s0[j], w0j = w0[j];
    const float eRj = __expf(-(rlo0 + rlo1));   // exp(-rB_lo[j])
    const float eDj = __expf(-(dlo0 + dlo1));

    // ---- phase A3: i-side precompute, warp-cooperative (warp w -> node i0+w) ----
    {
        const int i = i0 + wid;
        const float* ei = embs + (size_t)i * CC;
        const float a = ei[lane], b = ei[lane + 32];
        float rh = fmaf(a, __ldg(rf + CC + lane), b * __ldg(rf + CC + 32 + lane));
        float dh = fmaf(a, __ldg(df + CC + lane), b * __ldg(df + CC + 32 + lane));
#pragma unroll
        for (int off = 16; off > 0; off >>= 1) {
            rh += __shfl_xor_sync(0xFFFFFFFFu, rh, off);
            dh += __shfl_xor_sync(0xFFFFFFFFu, dh, off);
        }
        if (lane == 0) {
            sPosI[wid]  = make_float4(X[3*i], X[3*i+1], X[3*i+2], s0[i]);
            sMiscI[wid] = make_float4(w0[i], __expf(-rh), __expf(-dh), 0.f);
        }
    }
    __syncthreads();

    // ---- phase B: pairwise energy (fully unrolled, masks already in regs) ----
    float acc = 0.f;
#pragma unroll
    for (int k = 0; k < ICH; k++) {
        const float4 pi = sPosI[k];
        const float4 mi = sMiscI[k];

        const float dx = xj - pi.x;
        const float dy = yj - pi.y;
        const float dz = zj - pi.z;
        const float r2 = fmaf(dx, dx, fmaf(dy, dy, fmaf(dz, dz, 3e-6f)));
        const float D  = sqrt_approx(r2);

        // sigmoid(a_i + b_j) = 1 / (1 + exp(-a_i)*exp(-b_j))
        const float sr = rcp_approx(fmaf(mi.y, eRj, 1.f));
        const float sd = rcp_approx(fmaf(mi.z, eDj, 1.f));

        const float s  = (pi.w + s0j) * fmaf(0.8f, sr, 0.4f);
        const float Dm = D - s;

        // attr*3 = t*u + t^3 + t^10,  t = exp(-Dm^2), u = exp(0.6 Dm - 0.09)
        const float t   = __expf(-Dm * Dm);
        const float u   = __expf(fmaf(0.6f, Dm, -0.09f));
        const float t2  = t * t;
        const float t3  = t2 * t;
        const float t4  = t2 * t2;
        const float t8  = t4 * t4;
        const float t10 = t8 * t2;
        const float attr3 = fmaf(t, u, t3 + t10);

        const float w = sqrt_approx(fmaf(mi.x, w0j, 1e-6f)) * (sd + 0.5f);

        // repl = 5 * exp(-0.3 * D^3),  D^3 = D * r2
        const float repl = 5.f * __expf(-0.3f * D * r2);

        acc += mk[k] * fmaf(-w * (1.f / 3.f), attr3, repl);
    }

    // ---- block reduction ----
    sred[tid] = acc;
    __syncthreads();
#pragma unroll
    for (int off = NT / 2; off >= 32; off >>= 1) {
        if (tid < off) sred[tid] += sred[tid + off];
        __syncthreads();
    }
    if (tid < 32) {
        float v = sred[tid];
#pragma unroll
        for (int off = 16; off > 0; off >>= 1)
            v += __shfl_down_sync(0xFFFFFFFFu, v, off);

        if (tid == 0) {
            const int bucket = (blockIdx.y * GX + blockIdx.x) & (NBUCK - 1);
            atomicAdd(&g_accs[bucket], (double)v);
            __threadfence();
            const unsigned prev = atomicAdd(&g_count, 1u);
            if (prev == NBLK - 1) {
                __threadfence();
                double total = 0.0;
#pragma unroll
                for (int b = 0; b < NBUCK; b++) {
                    total += g_accs[b];
                    g_accs[b] = 0.0;     // reset for next graph replay
                }
                const float r = (float)total;
                out[0] = isnan(r) ? 1e-6f : r;
                g_count = 0u;
            }
        }
    }
}

extern "C" void kernel_launch(void* const* d_in, const int* in_sizes, int n_in,
                              void* d_out, int out_size) {
    const float* X    = (const float*)d_in[0];  // (1, N, 3)
    const float* embs = (const float*)d_in[1];  // (1, N, C)
    const float* w0   = (const float*)d_in[2];  // (N,)
    const float* s0   = (const float*)d_in[3];  // (N,)
    const float* mask = (const float*)d_in[4];  // (1, N, N)
    const float* df   = (const float*)d_in[5];  // (2C, 1)
    const float* rf   = (const float*)d_in[6];  // (2C, 1)
    float* out = (float*)d_out;

    dim3 grid(GX, GY);   // 8 x 256 = 2048 blocks
    fused_kernel<<<grid, NT>>>(X, embs, w0, s0, mask, df, rf, out);
}

// round 4
// speedup vs baseline: 2.1990x; 2.1990x over previous
#include <cuda_runtime.h>
#include <math.h>

#define NN   2048
#define CC   64
#define NT   256           // j-threads per block
#define ICH  16            // i rows per block
#define GX   (NN / NT)     // 8
#define GY   (NN / ICH)    // 128
#define NBLK (GX * GY)     // 1024
#define NBUCK 64

// ---- device scratch ----
__device__ float4   g_pos[NN];   // x, y, z, s0
__device__ float4   g_exp[NN];   // exp(-r_lo), exp(-d_lo), exp(-r_hi), exp(-d_hi)
__device__ float    g_w0[NN];
__device__ double   g_accs[NBUCK];  // zero at load; reset by last block
__device__ unsigned g_count;        // zero at load; reset by last block

__device__ __forceinline__ float sqrt_approx(float x) {
    float r; asm("sqrt.approx.f32 %0, %1;" : "=f"(r) : "f"(x)); return r;
}
__device__ __forceinline__ float rcp_approx(float x) {
    float r; asm("rcp.approx.f32 %0, %1;" : "=f"(r) : "f"(x)); return r;
}

// ---- per-node precompute: 4 dots (len 64) + 4 exps, once per node ----
__global__ void __launch_bounds__(256) pre_kernel(
    const float* __restrict__ X,
    const float* __restrict__ embs,
    const float* __restrict__ w0,
    const float* __restrict__ s0,
    const float* __restrict__ df,
    const float* __restrict__ rf)
{
    const int n = blockIdx.x * blockDim.x + threadIdx.x;
    if (n >= NN) return;
    const float4* e = (const float4*)(embs + (size_t)n * CC);
    float rl = 0.f, rh = 0.f, dl = 0.f, dh = 0.f;
#pragma unroll
    for (int c = 0; c < CC / 4; c++) {
        const float4 v = e[c];
        rl = fmaf(v.x, __ldg(rf + 4*c + 0), rl);
        rl = fmaf(v.y, __ldg(rf + 4*c + 1), rl);
        rl = fmaf(v.z, __ldg(rf + 4*c + 2), rl);
        rl = fmaf(v.w, __ldg(rf + 4*c + 3), rl);
        rh = fmaf(v.x, __ldg(rf + CC + 4*c + 0), rh);
        rh = fmaf(v.y, __ldg(rf + CC + 4*c + 1), rh);
        rh = fmaf(v.z, __ldg(rf + CC + 4*c + 2), rh);
        rh = fmaf(v.w, __ldg(rf + CC + 4*c + 3), rh);
        dl = fmaf(v.x, __ldg(df + 4*c + 0), dl);
        dl = fmaf(v.y, __ldg(df + 4*c + 1), dl);
        dl = fmaf(v.z, __ldg(df + 4*c + 2), dl);
        dl = fmaf(v.w, __ldg(df + 4*c + 3), dl);
        dh = fmaf(v.x, __ldg(df + CC + 4*c + 0), dh);
        dh = fmaf(v.y, __ldg(df + CC + 4*c + 1), dh);
        dh = fmaf(v.z, __ldg(df + CC + 4*c + 2), dh);
        dh = fmaf(v.w, __ldg(df + CC + 4*c + 3), dh);
    }
    g_pos[n] = make_float4(X[3*n], X[3*n+1], X[3*n+2], s0[n]);
    g_exp[n] = make_float4(__expf(-rl), __expf(-dl), __expf(-rh), __expf(-dh));
    g_w0[n]  = w0[n];
}

// ---- pairwise energy ----
__global__ void __launch_bounds__(NT) pair_kernel(
    const float* __restrict__ mask, float* __restrict__ out)
{
    const int tid = threadIdx.x;
    const int j   = blockIdx.x * NT + tid;
    const int i0  = blockIdx.y * ICH;

    __shared__ float4 sPosI[ICH];   // x, y, z, s0
    __shared__ float4 sMiscI[ICH];  // w0, exp(-r_hi), exp(-d_hi), pad
    __shared__ float  sred[NT];

    // stage i-side node data into shared (threads 0..31)
    if (tid < ICH) {
        sPosI[tid] = g_pos[i0 + tid];
    } else if (tid >= 32 && tid < 32 + ICH) {
        const int i = i0 + (tid - 32);
        const float4 e = g_exp[i];
        sMiscI[tid - 32] = make_float4(g_w0[i], e.z, e.w, 0.f);
    }

    // j-side node data (coalesced float4 reads)
    const float4 pj = g_pos[j];     // xj, yj, zj, s0j
    const float4 ej = g_exp[j];     // eRlo, eDlo, -, -
    const float  w0j = g_w0[j];

    // prefetch first mask group (MLP = 8)
    float mk[8], mk2[8];
#pragma unroll
    for (int k = 0; k < 8; k++)
        mk[k] = __ldg(mask + (size_t)(i0 + k) * NN + j);

    __syncthreads();

    float acc = 0.f;
#pragma unroll
    for (int g = 0; g < ICH / 8; g++) {
        // prefetch next group while computing this one
        if (g + 1 < ICH / 8) {
#pragma unroll
            for (int k = 0; k < 8; k++)
                mk2[k] = __ldg(mask + (size_t)(i0 + (g + 1) * 8 + k) * NN + j);
        }
#pragma unroll
        for (int k = 0; k < 8; k++) {
            const int kk = g * 8 + k;
            const float4 pi = sPosI[kk];
            const float4 mi = sMiscI[kk];

            const float dx = pj.x - pi.x;
            const float dy = pj.y - pi.y;
            const float dz = pj.z - pi.z;
            const float r2 = fmaf(dx, dx, fmaf(dy, dy, fmaf(dz, dz, 3e-6f)));
            const float D  = sqrt_approx(r2);

            // sigmoid(a_i + b_j) = 1 / (1 + exp(-a_i) * exp(-b_j))
            const float sr = rcp_approx(fmaf(mi.y, ej.x, 1.f));
            const float sd = rcp_approx(fmaf(mi.z, ej.y, 1.f));

            const float s  = (pi.w + pj.w) * fmaf(0.8f, sr, 0.4f);
            const float Dm = D - s;

            // attr*3 = t*u + t^3 + t^10,  t = exp(-Dm^2), u = exp(0.6 Dm - 0.09)
            const float t   = __expf(-Dm * Dm);
            const float u   = __expf(fmaf(0.6f, Dm, -0.09f));
            const float t2  = t * t;
            const float t3  = t2 * t;
            const float t4  = t2 * t2;
            const float t8  = t4 * t4;
            const float t10 = t8 * t2;
            const float attr3 = fmaf(t, u, t3 + t10);

            const float w = sqrt_approx(fmaf(mi.x, w0j, 1e-6f)) * (sd + 0.5f);

            // repl = 5 * exp(-0.3 * D^3),  D^3 = D * r2
            const float repl = 5.f * __expf(-0.3f * D * r2);

            acc += mk[k] * fmaf(-w * (1.f / 3.f), attr3, repl);
        }
#pragma unroll
        for (int k = 0; k < 8; k++) mk[k] = mk2[k];
    }

    // ---- block reduction ----
    sred[tid] = acc;
    __syncthreads();
#pragma unroll
    for (int off = NT / 2; off >= 32; off >>= 1) {
        if (tid < off) sred[tid] += sred[tid + off];
        __syncthreads();
    }
    if (tid < 32) {
        float v = sred[tid];
#pragma unroll
        for (int off = 16; off > 0; off >>= 1)
            v += __shfl_down_sync(0xFFFFFFFFu, v, off);

        if (tid == 0) {
            const int bucket = (blockIdx.y * GX + blockIdx.x) & (NBUCK - 1);
            atomicAdd(&g_accs[bucket], (double)v);
            __threadfence();
            const unsigned prev = atomicAdd(&g_count, 1u);
            if (prev == NBLK - 1) {
                __threadfence();
                double total = 0.0;
#pragma unroll
                for (int b = 0; b < NBUCK; b++) {
                    total += g_accs[b];
                    g_accs[b] = 0.0;     // reset for next graph replay
                }
                const float r = (float)total;
                out[0] = isnan(r) ? 1e-6f : r;
                g_count = 0u;
            }
        }
    }
}

extern "C" void kernel_launch(void* const* d_in, const int* in_sizes, int n_in,
                              void* d_out, int out_size) {
    const float* X    = (const float*)d_in[0];  // (1, N, 3)
    const float* embs = (const float*)d_in[1];  // (1, N, C)
    const float* w0   = (const float*)d_in[2];  // (N,)
    const float* s0   = (const float*)d_in[3];  // (N,)
    const float* mask = (const float*)d_in[4];  // (1, N, N)
    const float* df   = (const float*)d_in[5];  // (2C, 1)
    const float* rf   = (const float*)d_in[6];  // (2C, 1)
    float* out = (float*)d_out;

    pre_kernel<<<NN / 256, 256>>>(X, embs, w0, s0, df, rf);
    dim3 grid(GX, GY);   // 8 x 128 = 1024 blocks
    pair_kernel<<<grid, NT>>>(mask, out);
}